// round 10
// baseline (speedup 1.0000x reference)
#include <cuda_runtime.h>
#include <cuda_bf16.h>
#include <cstdint>
#include <cstring>

// BatchHardLoss round 9: INT8 mma.sync m16n8k32 (s32 acc, exact), symmetry
// (upper triangle), R6 pipeline (3-deep ring, 1 barrier/chunk, deferred
// epilogue), magic-constant int->float in poly-exp epilogue, bf16 corr kernel.
// (R8 with bitcast helpers replacing nonexistent __bfloat162_as_uint.)

#define BATCH 8192
#define DIMK  256
#define NCLS  512
#define GAMMA 0.001f
#define QSCALE 24.0f
#define MAGICI 0x4B400000        // 12582912.0f ; exact int add for |v| < 2^22
#define MAGICF 12582912.0f

static __device__ float g_all[BATCH];
static __device__ float g_pos[BATCH];
static __device__ float g_same[BATCH];
static __device__ int   g_cnt[NCLS];
static __device__ int   g_members[NCLS * 16];
static __device__ unsigned char g_Xq[BATCH * DIMK];   // s8, x*24 rounded

constexpr int BM = 128;
constexpr int NBLK = BATCH / BM;             // 64
constexpr int GRID = 296;                    // 8 CTAs x8 pairs + 288 x7 = 2080
constexpr int KCHUNK = 16384;                // 128 rows x 128B SW128 chunk
constexpr int ATILE = 32768;                 // A resident: 128 x 256 s8 (2 chunks)
constexpr int SMEM_DYN = ATILE + 3 * KCHUNK; // 80KB

#define SW128(o) ((o) ^ (((o) >> 3) & 0x70))

__device__ __forceinline__ uint32_t bf2_as_u32(__nv_bfloat162 v) {
    uint32_t r; memcpy(&r, &v, 4); return r;
}
__device__ __forceinline__ __nv_bfloat162 u32_as_bf2(uint32_t v) {
    __nv_bfloat162 r; memcpy(&r, &v, 4); return r;
}

__device__ __forceinline__ void cp_async16(uint32_t dst, const void* src) {
    asm volatile("cp.async.cg.shared.global [%0], [%1], 16;\n" :: "r"(dst), "l"(src));
}
#define CP_COMMIT() asm volatile("cp.async.commit_group;\n" ::: "memory")
#define CP_WAIT(N)  asm volatile("cp.async.wait_group %0;\n" :: "n"(N) : "memory")

#define PACK2(d, a, b)    asm("mov.b64 %0, {%1,%2};" : "=l"(d) : "f"(a), "f"(b))
#define UNPACK2(a, b, s)  asm("mov.b64 {%0,%1}, %2;" : "=f"(a), "=f"(b) : "l"(s))
#define ADD2(d, a, b)     asm("add.rn.f32x2 %0, %1, %2;" : "=l"(d) : "l"(a), "l"(b))
#define FMA2(d, a, b, c)  asm("fma.rn.f32x2 %0, %1, %2, %3;" : "=l"(d) : "l"(a), "l"(b), "l"(c))

// ---------------- small kernels ----------------

__global__ void bhl_zero_cnt_kernel() {
    int i = threadIdx.x + blockIdx.x * blockDim.x;
    if (i < NCLS) g_cnt[i] = 0;
}

__global__ void bhl_convert_kernel(const float* __restrict__ X,
                                   const int* __restrict__ T,
                                   float* __restrict__ out) {
    int i = blockIdx.x * blockDim.x + threadIdx.x;   // float4 index
    float4 v = ((const float4*)X)[i];
    int q0 = max(-127, min(127, __float2int_rn(v.x * QSCALE)));
    int q1 = max(-127, min(127, __float2int_rn(v.y * QSCALE)));
    int q2 = max(-127, min(127, __float2int_rn(v.z * QSCALE)));
    int q3 = max(-127, min(127, __float2int_rn(v.w * QSCALE)));
    uint32_t p = (uint32_t)(q0 & 0xFF) | ((uint32_t)(q1 & 0xFF) << 8)
               | ((uint32_t)(q2 & 0xFF) << 16) | ((uint32_t)(q3 & 0xFF) << 24);
    ((uint32_t*)g_Xq)[i] = p;
    if (i < BATCH) {
        g_all[i] = 0.0f;
        int c = T[i];
        int s = atomicAdd(&g_cnt[c], 1);
        if (s < 16) g_members[c * 16 + s] = i;
    }
    if (i == 0) out[0] = 0.0f;
}

// ---------------- main kernel ----------------

// A tile: 128 rows x 256B (full K in s8) into 2 SW128 chunks
__device__ __forceinline__ void load_tileA(uint32_t sdst, const char* srcRow0, int tid) {
#pragma unroll
    for (int i = 0; i < 8; i++) {
        int s = i * 256 + tid;            // 16B segment 0..2047
        int row = s >> 4;
        int seg = s & 15;                 // 0..15
        int chunk = seg >> 3, w = seg & 7;
        uint32_t soff = chunk * KCHUNK + SW128(row * 128 + w * 16);
        cp_async16(sdst + soff, srcRow0 + (size_t)row * 256 + seg * 16);
    }
}

// one B k-chunk: 128 rows x 128B (k elements kc*128 .. +127)
__device__ __forceinline__ void load_chunkB(uint32_t sdst, const char* srcRow0, int kc, int tid) {
#pragma unroll
    for (int i = 0; i < 4; i++) {
        int s = i * 256 + tid;            // 0..1023
        int n = s >> 3, w = s & 7;
        uint32_t soff = SW128(n * 128 + w * 16);
        cp_async16(sdst + soff, srcRow0 + (size_t)n * 256 + kc * 128 + w * 16);
    }
}

__global__ __launch_bounds__(256, 2)
void bhl_main_kernel() {
    extern __shared__ char dynsmem[];

    const int tid  = threadIdx.x;
    const int lane = tid & 31;
    const int wid  = tid >> 5;
    const int wm   = wid >> 2;
    const int wn   = wid & 3;
    const int bid  = blockIdx.x;

    const int pstart = bid * 7 + min(bid, 8);
    const int pcount = 7 + (bid < 8 ? 1 : 0);

    int I = 0, s = 0;
    while (s + (NBLK - I) <= pstart) { s += NBLK - I; I++; }
    int J = I + (pstart - s);

    const uint32_t sb = (uint32_t)__cvta_generic_to_shared(dynsmem);
    const uint32_t aBase = sb;
    const uint32_t bBase = sb + ATILE;

    const char* Xq = (const char*)g_Xq;

    load_tileA(aBase, Xq + (size_t)I * BM * 256, tid);
    load_chunkB(bBase, Xq + (size_t)J * BM * 256, 0, tid);
    CP_COMMIT();
    load_chunkB(bBase + KCHUNK, Xq + (size_t)J * BM * 256, 1, tid);
    CP_COMMIT();

    int acc[4][4][4];
#pragma unroll
    for (int a = 0; a < 4; a++)
#pragma unroll
        for (int b = 0; b < 4; b++)
#pragma unroll
            for (int c = 0; c < 4; c++) acc[a][b][c] = 0;

    unsigned long long G2, B2, P4, P3, P2, ONE2, ZERO2;
    unsigned long long accR[8], colAcc[4];
    {
        const float gp = GAMMA / (QSCALE * QSCALE);      // gamma' for int units
        const float bb = -gp * MAGICF;                   // beta: absorbs magic bias
        const float c4 = 1.0f / 24.0f, c3 = 1.0f / 6.0f, c2 = 0.5f, o = 1.0f, z = 0.0f;
        PACK2(G2, gp, gp); PACK2(B2, bb, bb);
        PACK2(P4, c4, c4); PACK2(P3, c3, c3); PACK2(P2, c2, c2);
        PACK2(ONE2, o, o); PACK2(ZERO2, z, z);
#pragma unroll
        for (int i = 0; i < 8; i++) accR[i] = ZERO2;
#pragma unroll
        for (int i = 0; i < 4; i++) colAcc[i] = ZERO2;
    }

    int oldI = 0, oldJ = 0;
    bool haveOld = false;
    bool reloadedA = false;
    int gchunk = 0;

    auto epilogue_and_colflush = [&]() {
#pragma unroll
        for (int mt = 0; mt < 4; mt++) {
#pragma unroll
            for (int nt = 0; nt < 4; nt++) {
                unsigned long long d2, w2, e2;
                int v0 = acc[mt][nt][0] + MAGICI;
                int v1 = acc[mt][nt][1] + MAGICI;
                PACK2(d2, __int_as_float(v0), __int_as_float(v1));
                FMA2(w2, d2, G2, B2);              // w = gamma*W (fp32)
                FMA2(e2, w2, P4, P3);
                FMA2(e2, e2, w2, P2);
                FMA2(e2, e2, w2, ONE2);
                FMA2(e2, e2, w2, ONE2);
                ADD2(accR[mt * 2], accR[mt * 2], e2);
                ADD2(colAcc[nt], colAcc[nt], e2);

                int v2 = acc[mt][nt][2] + MAGICI;
                int v3 = acc[mt][nt][3] + MAGICI;
                PACK2(d2, __int_as_float(v2), __int_as_float(v3));
                FMA2(w2, d2, G2, B2);
                FMA2(e2, w2, P4, P3);
                FMA2(e2, e2, w2, P2);
                FMA2(e2, e2, w2, ONE2);
                FMA2(e2, e2, w2, ONE2);
                ADD2(accR[mt * 2 + 1], accR[mt * 2 + 1], e2);
                ADD2(colAcc[nt], colAcc[nt], e2);
            }
        }
        if (oldI != oldJ) {
#pragma unroll
            for (int nt = 0; nt < 4; nt++) {
                float vlo, vhi;
                UNPACK2(vlo, vhi, colAcc[nt]);
#pragma unroll
                for (int o = 4; o <= 16; o <<= 1) {
                    vlo += __shfl_xor_sync(0xffffffffu, vlo, o);
                    vhi += __shfl_xor_sync(0xffffffffu, vhi, o);
                }
                if (lane < 4) {
                    atomicAdd(&g_all[oldJ * BM + wn * 32 + nt * 8 + 2 * lane], vlo);
                    atomicAdd(&g_all[oldJ * BM + wn * 32 + nt * 8 + 2 * lane + 1], vhi);
                }
                colAcc[nt] = ZERO2;
            }
        } else {
#pragma unroll
            for (int nt = 0; nt < 4; nt++) colAcc[nt] = ZERO2;
        }
    };

    auto rowflush = [&](int Iblk) {
#pragma unroll
        for (int i = 0; i < 8; i++) {
            float vlo, vhi;
            UNPACK2(vlo, vhi, accR[i]);
            float v = vlo + vhi;
            v += __shfl_xor_sync(0xffffffffu, v, 1);
            v += __shfl_xor_sync(0xffffffffu, v, 2);
            if ((lane & 3) == 0) {
                int r = wm * 64 + (i >> 1) * 16 + (lane >> 2) + (i & 1) * 8;
                atomicAdd(&g_all[Iblk * BM + r], v);
            }
            accR[i] = ZERO2;
        }
    };

    for (int pi = 0; pi < pcount; ++pi) {
        const bool last = (pi == pcount - 1);
        int In = I, Jn = J + 1;
        if (Jn == NBLK) { In = I + 1; Jn = In; }
        const char* BrowN = Xq + (size_t)Jn * BM * 256;

#pragma unroll
        for (int kc = 0; kc < 2; kc++) {
            if (kc == 0 && reloadedA) { CP_WAIT(0); reloadedA = false; }
            else { CP_WAIT(1); }
            __syncthreads();

            if (kc == 0 && haveOld) { epilogue_and_colflush(); haveOld = false; }

            const uint32_t aC = aBase + (uint32_t)kc * KCHUNK;
            const uint32_t bC = bBase + (uint32_t)(gchunk % 3) * KCHUNK;

#pragma unroll
            for (int ks = 0; ks < 4; ks++) {
                uint32_t af[4][4];
#pragma unroll
                for (int mt = 0; mt < 4; mt++) {
                    int row = wm * 64 + mt * 16 + (lane & 15);
                    int kseg = ks * 2 + (lane >> 4);
                    uint32_t addr = aC + SW128(row * 128 + kseg * 16);
                    asm volatile("ldmatrix.sync.aligned.m8n8.x4.shared.b16 {%0,%1,%2,%3}, [%4];\n"
                                 : "=r"(af[mt][0]), "=r"(af[mt][1]), "=r"(af[mt][2]), "=r"(af[mt][3])
                                 : "r"(addr));
                }
#pragma unroll
                for (int nt = 0; nt < 4; nt++) {
                    int n = wn * 32 + nt * 8 + (lane & 7);
                    int kseg = ks * 2 + ((lane >> 3) & 1);
                    uint32_t b0, b1;
                    uint32_t addr = bC + SW128(n * 128 + kseg * 16);
                    asm volatile("ldmatrix.sync.aligned.m8n8.x2.shared.b16 {%0,%1}, [%2];\n"
                                 : "=r"(b0), "=r"(b1) : "r"(addr));
                    if (kc == 0 && ks == 0) {
#pragma unroll
                        for (int mt = 0; mt < 4; mt++) {
                            asm volatile(
                                "mma.sync.aligned.m16n8k32.row.col.s32.s8.s8.s32 "
                                "{%0,%1,%2,%3}, {%4,%5,%6,%7}, {%8,%9}, {%10,%10,%10,%10};\n"
                                : "=r"(acc[mt][nt][0]), "=r"(acc[mt][nt][1]),
                                  "=r"(acc[mt][nt][2]), "=r"(acc[mt][nt][3])
                                : "r"(af[mt][0]), "r"(af[mt][1]), "r"(af[mt][2]), "r"(af[mt][3]),
                                  "r"(b0), "r"(b1), "r"(0));
                        }
                    } else {
#pragma unroll
                        for (int mt = 0; mt < 4; mt++) {
                            asm volatile(
                                "mma.sync.aligned.m16n8k32.row.col.s32.s8.s8.s32 "
                                "{%0,%1,%2,%3}, {%4,%5,%6,%7}, {%8,%9}, {%0,%1,%2,%3};\n"
                                : "+r"(acc[mt][nt][0]), "+r"(acc[mt][nt][1]),
                                  "+r"(acc[mt][nt][2]), "+r"(acc[mt][nt][3])
                                : "r"(af[mt][0]), "r"(af[mt][1]), "r"(af[mt][2]), "r"(af[mt][3]),
                                  "r"(b0), "r"(b1));
                        }
                    }
                }
            }

            // prefetch next pair's chunk kc into ring slot (gchunk+2)%3
            if (!last) {
                load_chunkB(bBase + (uint32_t)((gchunk + 2) % 3) * KCHUNK, BrowN, kc, tid);
            }
            CP_COMMIT();
            gchunk++;
        }

        oldI = I; oldJ = J; haveOld = true;

        if (last) {
            epilogue_and_colflush(); haveOld = false;
            rowflush(I);
        } else if (In != I) {
            __syncthreads();
            epilogue_and_colflush(); haveOld = false;
            rowflush(I);
            load_tileA(aBase, Xq + (size_t)In * BM * 256, tid);
            CP_COMMIT();
            reloadedA = true;
        }
        I = In; J = Jn;
    }
}

// ---------------- same-class correction (bf16 rows, fp32 accumulate) ----------------

__global__ __launch_bounds__(256)
void bhl_corr_kernel(const float* __restrict__ X) {
    __shared__ uint32_t rows[16][132];      // 128 bf16x2 words used per row
    __shared__ int sm[16];
    const int c = blockIdx.x, tid = threadIdx.x;
    int K = g_cnt[c];
    if (K > 16) K = 16;
    if (tid < 16) sm[tid] = (tid < K) ? g_members[c * 16 + tid] : 0;
    __syncthreads();
#pragma unroll
    for (int f = tid; f < 512; f += 256) {
        int row = f >> 5, q = f & 31;       // q: 8-dim group
        const float* p = X + (size_t)sm[row] * DIMK + q * 8;
        float4 a = *(const float4*)p;
        float4 b = *(const float4*)(p + 4);
        uint32_t w0 = bf2_as_u32(__floats2bfloat162_rn(a.x, a.y));
        uint32_t w1 = bf2_as_u32(__floats2bfloat162_rn(a.z, a.w));
        uint32_t w2 = bf2_as_u32(__floats2bfloat162_rn(b.x, b.y));
        uint32_t w3 = bf2_as_u32(__floats2bfloat162_rn(b.z, b.w));
        *(uint4*)&rows[row][q * 4] = make_uint4(w0, w1, w2, w3);
    }
    __syncthreads();
    const int i = tid >> 4, j = tid & 15;
    const uint4* ri = (const uint4*)&rows[i][0];
    const uint4* rj = (const uint4*)&rows[j][0];
    float dot = 0.0f;
#pragma unroll
    for (int t = 0; t < 8; t++) {
        uint4 a = ri[t], b = rj[t];
        float2 fa, fb;
        fa = __bfloat1622float2(u32_as_bf2(a.x));
        fb = __bfloat1622float2(u32_as_bf2(b.x));
        dot += fa.x * fb.x + fa.y * fb.y;
        fa = __bfloat1622float2(u32_as_bf2(a.y));
        fb = __bfloat1622float2(u32_as_bf2(b.y));
        dot += fa.x * fb.x + fa.y * fb.y;
        fa = __bfloat1622float2(u32_as_bf2(a.z));
        fb = __bfloat1622float2(u32_as_bf2(b.z));
        dot += fa.x * fb.x + fa.y * fb.y;
        fa = __bfloat1622float2(u32_as_bf2(a.w));
        fb = __bfloat1622float2(u32_as_bf2(b.w));
        dot += fa.x * fb.x + fa.y * fb.y;
    }
    float w = fminf(fmaxf(dot * GAMMA, -16.0f), 16.0f);
    const bool valid = (i < K) && (j < K);
    float epos  = (valid && i != j) ? __expf(-w) : 0.0f;
    float esame = valid ? __expf(w) : 0.0f;
#pragma unroll
    for (int o = 8; o; o >>= 1) {
        epos  += __shfl_xor_sync(0xffffffffu, epos, o);
        esame += __shfl_xor_sync(0xffffffffu, esame, o);
    }
    if (j == 0 && i < K) {
        g_pos[sm[i]]  = epos;
        g_same[sm[i]] = esame;
    }
}

__global__ void bhl_finalize_kernel(float* __restrict__ out) {
    __shared__ float red[256];
    const int tid = threadIdx.x;
    const int r = blockIdx.x * 256 + tid;
    red[tid] = __logf(g_pos[r] * (g_all[r] - g_same[r]));
    __syncthreads();
    for (int o = 128; o; o >>= 1) {
        if (tid < o) red[tid] += red[tid + o];
        __syncthreads();
    }
    if (tid == 0) atomicAdd(out, red[0] * (1.0f / (float)BATCH));
}

extern "C" void kernel_launch(void* const* d_in, const int* in_sizes, int n_in,
                              void* d_out, int out_size) {
    const float* X = (const float*)d_in[0];
    const int*   T = (const int*)d_in[1];
    float* out = (float*)d_out;

    cudaFuncSetAttribute(bhl_main_kernel, cudaFuncAttributeMaxDynamicSharedMemorySize, SMEM_DYN);

    bhl_zero_cnt_kernel<<<2, 256>>>();
    bhl_convert_kernel<<<(BATCH * DIMK / 4) / 256, 256>>>(X, T, out);
    bhl_corr_kernel<<<NCLS, 256>>>(X);
    bhl_main_kernel<<<GRID, 256, SMEM_DYN>>>();
    bhl_finalize_kernel<<<BATCH / 256, 256>>>(out);
}

// round 11
// speedup vs baseline: 2.4255x; 2.4255x over previous
#include <cuda_runtime.h>
#include <cuda_bf16.h>
#include <cstdint>
#include <cstring>

// BatchHardLoss round 10: R6 bf16 HMMA engine (proven 59.6us) + B ldmatrix.x4
// + corr kernel fused as tail CTAs of the main grid (bf16 rows) to hide it in
// the main kernel's drain phase.

#define BATCH 8192
#define DIMK  256
#define NCLS  512
#define GAMMA 0.001f

static __device__ float g_all[BATCH];
static __device__ float g_pos[BATCH];
static __device__ float g_same[BATCH];
static __device__ int   g_cnt[NCLS];
static __device__ int   g_members[NCLS * 16];
static __device__ __nv_bfloat16 g_Xb[BATCH * DIMK];

constexpr int BM = 128;
constexpr int NBLK = BATCH / BM;             // 64
constexpr int GRID_MAIN = 296;               // 8 x8 pairs + 288 x7 = 2080
constexpr int GRID_ALL  = GRID_MAIN + NCLS;  // + 512 corr blocks
constexpr int KCHUNK = 16384;                // 128 rows x 128B SW128 chunk
constexpr int ATILE = 65536;                 // A resident: 128 x 256 bf16
constexpr int SMEM_DYN = ATILE + 3 * KCHUNK; // 112KB

#define SW128(o) ((o) ^ (((o) >> 3) & 0x70))

__device__ __forceinline__ uint32_t bf2_as_u32(__nv_bfloat162 v) {
    uint32_t r; memcpy(&r, &v, 4); return r;
}
__device__ __forceinline__ __nv_bfloat162 u32_as_bf2(uint32_t v) {
    __nv_bfloat162 r; memcpy(&r, &v, 4); return r;
}

__device__ __forceinline__ void cp_async16(uint32_t dst, const void* src) {
    asm volatile("cp.async.cg.shared.global [%0], [%1], 16;\n" :: "r"(dst), "l"(src));
}
#define CP_COMMIT() asm volatile("cp.async.commit_group;\n" ::: "memory")
#define CP_WAIT(N)  asm volatile("cp.async.wait_group %0;\n" :: "n"(N) : "memory")

#define PACK2(d, a, b)    asm("mov.b64 %0, {%1,%2};" : "=l"(d) : "f"(a), "f"(b))
#define UNPACK2(a, b, s)  asm("mov.b64 {%0,%1}, %2;" : "=f"(a), "=f"(b) : "l"(s))
#define MUL2(d, a, b)     asm("mul.rn.f32x2 %0, %1, %2;" : "=l"(d) : "l"(a), "l"(b))
#define ADD2(d, a, b)     asm("add.rn.f32x2 %0, %1, %2;" : "=l"(d) : "l"(a), "l"(b))
#define FMA2(d, a, b, c)  asm("fma.rn.f32x2 %0, %1, %2, %3;" : "=l"(d) : "l"(a), "l"(b), "l"(c))

// ---------------- small kernels ----------------

__global__ void bhl_zero_cnt_kernel() {
    int i = threadIdx.x + blockIdx.x * blockDim.x;
    if (i < NCLS) g_cnt[i] = 0;
}

__global__ void bhl_convert_kernel(const float* __restrict__ X,
                                   const int* __restrict__ T,
                                   float* __restrict__ out) {
    int i = blockIdx.x * blockDim.x + threadIdx.x;   // float4 index
    float4 v = ((const float4*)X)[i];
    uint32_t lo = ((uint32_t)__bfloat16_as_ushort(__float2bfloat16_rn(v.y)) << 16)
                |  (uint32_t)__bfloat16_as_ushort(__float2bfloat16_rn(v.x));
    uint32_t hi = ((uint32_t)__bfloat16_as_ushort(__float2bfloat16_rn(v.w)) << 16)
                |  (uint32_t)__bfloat16_as_ushort(__float2bfloat16_rn(v.z));
    ((uint2*)g_Xb)[i] = make_uint2(lo, hi);
    if (i < BATCH) {
        g_all[i] = 0.0f;
        int c = T[i];
        int s = atomicAdd(&g_cnt[c], 1);
        if (s < 16) g_members[c * 16 + s] = i;
    }
    if (i == 0) out[0] = 0.0f;
}

// ---------------- tile loaders ----------------

__device__ __forceinline__ void load_tileA(uint32_t sdst, const char* srcRow0, int tid) {
#pragma unroll
    for (int i = 0; i < 16; i++) {
        int s = i * 256 + tid;
        int row = s >> 5;
        int seg = s & 31;
        int chunk = seg >> 3, w = seg & 7;
        uint32_t soff = chunk * KCHUNK + SW128(row * 128 + w * 16);
        cp_async16(sdst + soff, srcRow0 + (size_t)row * 512 + seg * 16);
    }
}

__device__ __forceinline__ void load_chunkB(uint32_t sdst, const char* srcRow0, int kc, int tid) {
#pragma unroll
    for (int i = 0; i < 4; i++) {
        int s = i * 256 + tid;
        int n = s >> 3, w = s & 7;
        uint32_t soff = SW128(n * 128 + w * 16);
        cp_async16(sdst + soff, srcRow0 + (size_t)n * 512 + kc * 128 + w * 16);
    }
}

// ---------------- corr path (tail CTAs): exact-ish bf16 gram per class ----------------

__device__ void corr_block(char* dynsmem, const float* __restrict__ X, int c, int tid) {
    uint32_t (*rows)[132] = (uint32_t(*)[132])dynsmem;        // 16 x 132 u32
    int* sm = (int*)(dynsmem + 16 * 132 * sizeof(uint32_t));
    int K = g_cnt[c];
    if (K > 16) K = 16;
    if (tid < 16) sm[tid] = (tid < K) ? g_members[c * 16 + tid] : 0;
    __syncthreads();
#pragma unroll
    for (int f = tid; f < 512; f += 256) {
        int row = f >> 5, q = f & 31;
        const float* p = X + (size_t)sm[row] * DIMK + q * 8;
        float4 a = *(const float4*)p;
        float4 b = *(const float4*)(p + 4);
        uint32_t w0 = bf2_as_u32(__floats2bfloat162_rn(a.x, a.y));
        uint32_t w1 = bf2_as_u32(__floats2bfloat162_rn(a.z, a.w));
        uint32_t w2 = bf2_as_u32(__floats2bfloat162_rn(b.x, b.y));
        uint32_t w3 = bf2_as_u32(__floats2bfloat162_rn(b.z, b.w));
        *(uint4*)&rows[row][q * 4] = make_uint4(w0, w1, w2, w3);
    }
    __syncthreads();
    const int i = tid >> 4, j = tid & 15;
    const uint4* ri = (const uint4*)&rows[i][0];
    const uint4* rj = (const uint4*)&rows[j][0];
    float dot = 0.0f;
#pragma unroll
    for (int t = 0; t < 8; t++) {
        uint4 a = ri[t], b = rj[t];
        float2 fa, fb;
        fa = __bfloat1622float2(u32_as_bf2(a.x)); fb = __bfloat1622float2(u32_as_bf2(b.x));
        dot += fa.x * fb.x + fa.y * fb.y;
        fa = __bfloat1622float2(u32_as_bf2(a.y)); fb = __bfloat1622float2(u32_as_bf2(b.y));
        dot += fa.x * fb.x + fa.y * fb.y;
        fa = __bfloat1622float2(u32_as_bf2(a.z)); fb = __bfloat1622float2(u32_as_bf2(b.z));
        dot += fa.x * fb.x + fa.y * fb.y;
        fa = __bfloat1622float2(u32_as_bf2(a.w)); fb = __bfloat1622float2(u32_as_bf2(b.w));
        dot += fa.x * fb.x + fa.y * fb.y;
    }
    float w = fminf(fmaxf(dot * GAMMA, -16.0f), 16.0f);
    const bool valid = (i < K) && (j < K);
    float epos  = (valid && i != j) ? __expf(-w) : 0.0f;
    float esame = valid ? __expf(w) : 0.0f;
#pragma unroll
    for (int o = 8; o; o >>= 1) {
        epos  += __shfl_xor_sync(0xffffffffu, epos, o);
        esame += __shfl_xor_sync(0xffffffffu, esame, o);
    }
    if (j == 0 && i < K) {
        g_pos[sm[i]]  = epos;
        g_same[sm[i]] = esame;
    }
}

// ---------------- main kernel ----------------

__global__ __launch_bounds__(256, 2)
void bhl_main_kernel(const float* __restrict__ X) {
    extern __shared__ char dynsmem[];

    const int tid  = threadIdx.x;
    const int bid  = blockIdx.x;

    if (bid >= GRID_MAIN) {                   // tail CTAs: per-class correction
        corr_block(dynsmem, X, bid - GRID_MAIN, tid);
        return;
    }

    const int lane = tid & 31;
    const int wid  = tid >> 5;
    const int wm   = wid >> 2;
    const int wn   = wid & 3;

    const int pstart = bid * 7 + min(bid, 8);
    const int pcount = 7 + (bid < 8 ? 1 : 0);

    int I = 0, s = 0;
    while (s + (NBLK - I) <= pstart) { s += NBLK - I; I++; }
    int J = I + (pstart - s);

    const uint32_t sb = (uint32_t)__cvta_generic_to_shared(dynsmem);
    const uint32_t aBase = sb;
    const uint32_t bBase = sb + ATILE;

    const char* Xb = (const char*)g_Xb;

    load_tileA(aBase, Xb + (size_t)I * BM * 512, tid);
    load_chunkB(bBase, Xb + (size_t)J * BM * 512, 0, tid);
    CP_COMMIT();
    load_chunkB(bBase + KCHUNK, Xb + (size_t)J * BM * 512, 1, tid);
    CP_COMMIT();

    float acc[4][4][4];
#pragma unroll
    for (int a = 0; a < 4; a++)
#pragma unroll
        for (int b = 0; b < 4; b++)
#pragma unroll
            for (int c = 0; c < 4; c++) acc[a][b][c] = 0.0f;

    unsigned long long G2, C4_2, C3_2, C2_2, ONE2, ZERO2;
    unsigned long long accR[8], colAcc[4];
    {
        const float g = GAMMA, c4 = 1.0f / 24.0f, c3 = 1.0f / 6.0f, c2 = 0.5f, o = 1.0f, z = 0.0f;
        PACK2(G2, g, g); PACK2(C4_2, c4, c4); PACK2(C3_2, c3, c3);
        PACK2(C2_2, c2, c2); PACK2(ONE2, o, o); PACK2(ZERO2, z, z);
#pragma unroll
        for (int i = 0; i < 8; i++) accR[i] = ZERO2;
#pragma unroll
        for (int i = 0; i < 4; i++) colAcc[i] = ZERO2;
    }
    const float zf = 0.0f;

    int oldI = 0, oldJ = 0;
    bool haveOld = false;
    bool reloadedA = false;
    int gchunk = 0;

    auto epilogue_and_colflush = [&]() {
#pragma unroll
        for (int mt = 0; mt < 4; mt++) {
#pragma unroll
            for (int nt = 0; nt < 4; nt++) {
                unsigned long long d2, w2, e2;
                PACK2(d2, acc[mt][nt][0], acc[mt][nt][1]);
                MUL2(w2, d2, G2);
                FMA2(e2, w2, C4_2, C3_2);
                FMA2(e2, e2, w2, C2_2);
                FMA2(e2, e2, w2, ONE2);
                FMA2(e2, e2, w2, ONE2);
                ADD2(accR[mt * 2], accR[mt * 2], e2);
                ADD2(colAcc[nt], colAcc[nt], e2);

                PACK2(d2, acc[mt][nt][2], acc[mt][nt][3]);
                MUL2(w2, d2, G2);
                FMA2(e2, w2, C4_2, C3_2);
                FMA2(e2, e2, w2, C2_2);
                FMA2(e2, e2, w2, ONE2);
                FMA2(e2, e2, w2, ONE2);
                ADD2(accR[mt * 2 + 1], accR[mt * 2 + 1], e2);
                ADD2(colAcc[nt], colAcc[nt], e2);
            }
        }
        if (oldI != oldJ) {
#pragma unroll
            for (int nt = 0; nt < 4; nt++) {
                float vlo, vhi;
                UNPACK2(vlo, vhi, colAcc[nt]);
#pragma unroll
                for (int o = 4; o <= 16; o <<= 1) {
                    vlo += __shfl_xor_sync(0xffffffffu, vlo, o);
                    vhi += __shfl_xor_sync(0xffffffffu, vhi, o);
                }
                if (lane < 4) {
                    atomicAdd(&g_all[oldJ * BM + wn * 32 + nt * 8 + 2 * lane], vlo);
                    atomicAdd(&g_all[oldJ * BM + wn * 32 + nt * 8 + 2 * lane + 1], vhi);
                }
                colAcc[nt] = ZERO2;
            }
        } else {
#pragma unroll
            for (int nt = 0; nt < 4; nt++) colAcc[nt] = ZERO2;
        }
    };

    auto rowflush = [&](int Iblk) {
#pragma unroll
        for (int i = 0; i < 8; i++) {
            float vlo, vhi;
            UNPACK2(vlo, vhi, accR[i]);
            float v = vlo + vhi;
            v += __shfl_xor_sync(0xffffffffu, v, 1);
            v += __shfl_xor_sync(0xffffffffu, v, 2);
            if ((lane & 3) == 0) {
                int r = wm * 64 + (i >> 1) * 16 + (lane >> 2) + (i & 1) * 8;
                atomicAdd(&g_all[Iblk * BM + r], v);
            }
            accR[i] = ZERO2;
        }
    };

    for (int pi = 0; pi < pcount; ++pi) {
        const bool last = (pi == pcount - 1);
        int In = I, Jn = J + 1;
        if (Jn == NBLK) { In = I + 1; Jn = In; }
        const char* Brow  = Xb + (size_t)J  * BM * 512;
        const char* BrowN = Xb + (size_t)Jn * BM * 512;

#pragma unroll
        for (int kc = 0; kc < 4; kc++) {
            if (kc == 0 && reloadedA) { CP_WAIT(0); reloadedA = false; }
            else { CP_WAIT(1); }
            __syncthreads();

            if (kc == 0 && haveOld) { epilogue_and_colflush(); haveOld = false; }

            const uint32_t aC = aBase + (uint32_t)kc * KCHUNK;
            const uint32_t bC = bBase + (uint32_t)(gchunk % 3) * KCHUNK;

#pragma unroll
            for (int ks = 0; ks < 4; ks++) {
                uint32_t af[4][4];
#pragma unroll
                for (int mt = 0; mt < 4; mt++) {
                    int row = wm * 64 + mt * 16 + (lane & 15);
                    int kseg = ks * 2 + (lane >> 4);
                    uint32_t addr = aC + SW128(row * 128 + kseg * 16);
                    asm volatile("ldmatrix.sync.aligned.m8n8.x4.shared.b16 {%0,%1,%2,%3}, [%4];\n"
                                 : "=r"(af[mt][0]), "=r"(af[mt][1]), "=r"(af[mt][2]), "=r"(af[mt][3])
                                 : "r"(addr));
                }
                // B: two x4 loads cover nt = {0,1} and {2,3}
#pragma unroll
                for (int np = 0; np < 2; np++) {
                    int g = lane >> 3, r = lane & 7;
                    int n = wn * 32 + np * 16 + (g >> 1) * 8 + r;
                    int kseg = ks * 2 + (g & 1);
                    uint32_t b0, b1, b2, b3;
                    uint32_t addr = bC + SW128(n * 128 + kseg * 16);
                    asm volatile("ldmatrix.sync.aligned.m8n8.x4.shared.b16 {%0,%1,%2,%3}, [%4];\n"
                                 : "=r"(b0), "=r"(b1), "=r"(b2), "=r"(b3) : "r"(addr));
                    if (kc == 0 && ks == 0) {
#pragma unroll
                        for (int mt = 0; mt < 4; mt++) {
                            asm volatile(
                                "mma.sync.aligned.m16n8k16.row.col.f32.bf16.bf16.f32 "
                                "{%0,%1,%2,%3}, {%4,%5,%6,%7}, {%8,%9}, {%10,%10,%10,%10};\n"
                                : "=f"(acc[mt][2 * np][0]), "=f"(acc[mt][2 * np][1]),
                                  "=f"(acc[mt][2 * np][2]), "=f"(acc[mt][2 * np][3])
                                : "r"(af[mt][0]), "r"(af[mt][1]), "r"(af[mt][2]), "r"(af[mt][3]),
                                  "r"(b0), "r"(b1), "f"(zf));
                            asm volatile(
                                "mma.sync.aligned.m16n8k16.row.col.f32.bf16.bf16.f32 "
                                "{%0,%1,%2,%3}, {%4,%5,%6,%7}, {%8,%9}, {%10,%10,%10,%10};\n"
                                : "=f"(acc[mt][2 * np + 1][0]), "=f"(acc[mt][2 * np + 1][1]),
                                  "=f"(acc[mt][2 * np + 1][2]), "=f"(acc[mt][2 * np + 1][3])
                                : "r"(af[mt][0]), "r"(af[mt][1]), "r"(af[mt][2]), "r"(af[mt][3]),
                                  "r"(b2), "r"(b3), "f"(zf));
                        }
                    } else {
#pragma unroll
                        for (int mt = 0; mt < 4; mt++) {
                            asm volatile(
                                "mma.sync.aligned.m16n8k16.row.col.f32.bf16.bf16.f32 "
                                "{%0,%1,%2,%3}, {%4,%5,%6,%7}, {%8,%9}, {%0,%1,%2,%3};\n"
                                : "+f"(acc[mt][2 * np][0]), "+f"(acc[mt][2 * np][1]),
                                  "+f"(acc[mt][2 * np][2]), "+f"(acc[mt][2 * np][3])
                                : "r"(af[mt][0]), "r"(af[mt][1]), "r"(af[mt][2]), "r"(af[mt][3]),
                                  "r"(b0), "r"(b1));
                            asm volatile(
                                "mma.sync.aligned.m16n8k16.row.col.f32.bf16.bf16.f32 "
                                "{%0,%1,%2,%3}, {%4,%5,%6,%7}, {%8,%9}, {%0,%1,%2,%3};\n"
                                : "+f"(acc[mt][2 * np + 1][0]), "+f"(acc[mt][2 * np + 1][1]),
                                  "+f"(acc[mt][2 * np + 1][2]), "+f"(acc[mt][2 * np + 1][3])
                                : "r"(af[mt][0]), "r"(af[mt][1]), "r"(af[mt][2]), "r"(af[mt][3]),
                                  "r"(b2), "r"(b3));
                        }
                    }
                }
            }

            uint32_t pSlot = bBase + (uint32_t)((gchunk + 2) % 3) * KCHUNK;
            if (kc < 2) {
                load_chunkB(pSlot, Brow, kc + 2, tid);
            } else if (!last) {
                load_chunkB(pSlot, BrowN, kc - 2, tid);
            }
            CP_COMMIT();
            gchunk++;
        }

        oldI = I; oldJ = J; haveOld = true;

        if (last) {
            epilogue_and_colflush(); haveOld = false;
            rowflush(I);
        } else if (In != I) {
            __syncthreads();
            epilogue_and_colflush(); haveOld = false;
            rowflush(I);
            load_tileA(aBase, Xb + (size_t)In * BM * 512, tid);
            CP_COMMIT();
            reloadedA = true;
        }
        I = In; J = Jn;
    }
}

__global__ void bhl_finalize_kernel(float* __restrict__ out) {
    __shared__ float red[256];
    const int tid = threadIdx.x;
    const int r = blockIdx.x * 256 + tid;
    red[tid] = __logf(g_pos[r] * (g_all[r] - g_same[r]));
    __syncthreads();
    for (int o = 128; o; o >>= 1) {
        if (tid < o) red[tid] += red[tid + o];
        __syncthreads();
    }
    if (tid == 0) atomicAdd(out, red[0] * (1.0f / (float)BATCH));
}

extern "C" void kernel_launch(void* const* d_in, const int* in_sizes, int n_in,
                              void* d_out, int out_size) {
    const float* X = (const float*)d_in[0];
    const int*   T = (const int*)d_in[1];
    float* out = (float*)d_out;

    cudaFuncSetAttribute(bhl_main_kernel, cudaFuncAttributeMaxDynamicSharedMemorySize, SMEM_DYN);

    bhl_zero_cnt_kernel<<<2, 256>>>();
    bhl_convert_kernel<<<(BATCH * DIMK / 4) / 256, 256>>>(X, T, out);
    bhl_main_kernel<<<GRID_ALL, 256, SMEM_DYN>>>(X);
    bhl_finalize_kernel<<<BATCH / 256, 256>>>(out);
}

// round 12
// speedup vs baseline: 2.5221x; 1.0398x over previous
#include <cuda_runtime.h>
#include <cuda_bf16.h>
#include <cuda_fp16.h>
#include <cstdint>
#include <cstring>

// BatchHardLoss round 11: bf16 HMMA with **f16 accumulators** (2x legacy-path
// rate hypothesis), 96KB smem (2 CTAs/SM), double-buffered B, deferred
// epilogue, fused corr tail CTAs, g_cnt self-reset (one less launch).

#define BATCH 8192
#define DIMK  256
#define NCLS  512
#define GAMMA 0.001f

static __device__ float g_all[BATCH];
static __device__ float g_pos[BATCH];
static __device__ float g_same[BATCH];
static __device__ int   g_cnt[NCLS];
static __device__ int   g_members[NCLS * 16];
static __device__ __nv_bfloat16 g_Xb[BATCH * DIMK];

constexpr int BM = 128;
constexpr int NBLK = BATCH / BM;             // 64
constexpr int GRID_MAIN = 296;               // 8 x8 pairs + 288 x7 = 2080
constexpr int GRID_ALL  = GRID_MAIN + NCLS;  // + 512 corr blocks
constexpr int KCHUNK = 16384;                // 128 rows x 128B SW128 chunk
constexpr int ATILE = 65536;                 // A resident: 128 x 256 bf16
constexpr int SMEM_DYN = ATILE + 2 * KCHUNK; // 96KB -> 2 CTAs/SM

#define SW128(o) ((o) ^ (((o) >> 3) & 0x70))

__device__ __forceinline__ uint32_t bf2_as_u32(__nv_bfloat162 v) {
    uint32_t r; memcpy(&r, &v, 4); return r;
}
__device__ __forceinline__ __nv_bfloat162 u32_as_bf2(uint32_t v) {
    __nv_bfloat162 r; memcpy(&r, &v, 4); return r;
}
__device__ __forceinline__ __half2 u32_as_h2(uint32_t v) {
    __half2 r; memcpy(&r, &v, 4); return r;
}

__device__ __forceinline__ void cp_async16(uint32_t dst, const void* src) {
    asm volatile("cp.async.cg.shared.global [%0], [%1], 16;\n" :: "r"(dst), "l"(src));
}
#define CP_COMMIT() asm volatile("cp.async.commit_group;\n" ::: "memory")
#define CP_WAIT(N)  asm volatile("cp.async.wait_group %0;\n" :: "n"(N) : "memory")

#define PACK2(d, a, b)    asm("mov.b64 %0, {%1,%2};" : "=l"(d) : "f"(a), "f"(b))
#define UNPACK2(a, b, s)  asm("mov.b64 {%0,%1}, %2;" : "=f"(a), "=f"(b) : "l"(s))
#define MUL2(d, a, b)     asm("mul.rn.f32x2 %0, %1, %2;" : "=l"(d) : "l"(a), "l"(b))
#define ADD2(d, a, b)     asm("add.rn.f32x2 %0, %1, %2;" : "=l"(d) : "l"(a), "l"(b))
#define FMA2(d, a, b, c)  asm("fma.rn.f32x2 %0, %1, %2, %3;" : "=l"(d) : "l"(a), "l"(b), "l"(c))

// ---------------- convert + bucket (also zeroes g_all/out) ----------------

__global__ void bhl_convert_kernel(const float* __restrict__ X,
                                   const int* __restrict__ T,
                                   float* __restrict__ out) {
    int i = blockIdx.x * blockDim.x + threadIdx.x;   // float4 index
    float4 v = ((const float4*)X)[i];
    uint32_t lo = ((uint32_t)__bfloat16_as_ushort(__float2bfloat16_rn(v.y)) << 16)
                |  (uint32_t)__bfloat16_as_ushort(__float2bfloat16_rn(v.x));
    uint32_t hi = ((uint32_t)__bfloat16_as_ushort(__float2bfloat16_rn(v.w)) << 16)
                |  (uint32_t)__bfloat16_as_ushort(__float2bfloat16_rn(v.z));
    ((uint2*)g_Xb)[i] = make_uint2(lo, hi);
    if (i < BATCH) {
        g_all[i] = 0.0f;
        int c = T[i];
        int s = atomicAdd(&g_cnt[c], 1);   // g_cnt starts 0 (init or corr reset)
        if (s < 16) g_members[c * 16 + s] = i;
    }
    if (i == 0) out[0] = 0.0f;
}

// ---------------- tile loaders ----------------

__device__ __forceinline__ void load_tileA(uint32_t sdst, const char* srcRow0, int tid) {
#pragma unroll
    for (int i = 0; i < 16; i++) {
        int s = i * 256 + tid;
        int row = s >> 5;
        int seg = s & 31;
        int chunk = seg >> 3, w = seg & 7;
        uint32_t soff = chunk * KCHUNK + SW128(row * 128 + w * 16);
        cp_async16(sdst + soff, srcRow0 + (size_t)row * 512 + seg * 16);
    }
}

__device__ __forceinline__ void load_chunkB(uint32_t sdst, const char* srcRow0, int kc, int tid) {
#pragma unroll
    for (int i = 0; i < 4; i++) {
        int s = i * 256 + tid;
        int n = s >> 3, w = s & 7;
        uint32_t soff = SW128(n * 128 + w * 16);
        cp_async16(sdst + soff, srcRow0 + (size_t)n * 512 + kc * 128 + w * 16);
    }
}

// ---------------- corr path (tail CTAs) ----------------

__device__ void corr_block(char* dynsmem, const float* __restrict__ X, int c, int tid) {
    uint32_t (*rows)[132] = (uint32_t(*)[132])dynsmem;
    int* sm = (int*)(dynsmem + 16 * 132 * sizeof(uint32_t));
    int K = g_cnt[c];
    if (K > 16) K = 16;
    if (tid < 16) sm[tid] = (tid < K) ? g_members[c * 16 + tid] : 0;
    __syncthreads();
    if (tid == 0) g_cnt[c] = 0;            // self-reset for next graph replay
#pragma unroll
    for (int f = tid; f < 512; f += 256) {
        int row = f >> 5, q = f & 31;
        const float* p = X + (size_t)sm[row] * DIMK + q * 8;
        float4 a = *(const float4*)p;
        float4 b = *(const float4*)(p + 4);
        uint32_t w0 = bf2_as_u32(__floats2bfloat162_rn(a.x, a.y));
        uint32_t w1 = bf2_as_u32(__floats2bfloat162_rn(a.z, a.w));
        uint32_t w2 = bf2_as_u32(__floats2bfloat162_rn(b.x, b.y));
        uint32_t w3 = bf2_as_u32(__floats2bfloat162_rn(b.z, b.w));
        *(uint4*)&rows[row][q * 4] = make_uint4(w0, w1, w2, w3);
    }
    __syncthreads();
    const int i = tid >> 4, j = tid & 15;
    const uint4* ri = (const uint4*)&rows[i][0];
    const uint4* rj = (const uint4*)&rows[j][0];
    float dot = 0.0f;
#pragma unroll
    for (int t = 0; t < 8; t++) {
        uint4 a = ri[t], b = rj[t];
        float2 fa, fb;
        fa = __bfloat1622float2(u32_as_bf2(a.x)); fb = __bfloat1622float2(u32_as_bf2(b.x));
        dot += fa.x * fb.x + fa.y * fb.y;
        fa = __bfloat1622float2(u32_as_bf2(a.y)); fb = __bfloat1622float2(u32_as_bf2(b.y));
        dot += fa.x * fb.x + fa.y * fb.y;
        fa = __bfloat1622float2(u32_as_bf2(a.z)); fb = __bfloat1622float2(u32_as_bf2(b.z));
        dot += fa.x * fb.x + fa.y * fb.y;
        fa = __bfloat1622float2(u32_as_bf2(a.w)); fb = __bfloat1622float2(u32_as_bf2(b.w));
        dot += fa.x * fb.x + fa.y * fb.y;
    }
    float w = fminf(fmaxf(dot * GAMMA, -16.0f), 16.0f);
    const bool valid = (i < K) && (j < K);
    float epos  = (valid && i != j) ? __expf(-w) : 0.0f;
    float esame = valid ? __expf(w) : 0.0f;
#pragma unroll
    for (int o = 8; o; o >>= 1) {
        epos  += __shfl_xor_sync(0xffffffffu, epos, o);
        esame += __shfl_xor_sync(0xffffffffu, esame, o);
    }
    if (j == 0 && i < K) {
        g_pos[sm[i]]  = epos;
        g_same[sm[i]] = esame;
    }
}

// ---------------- main kernel ----------------

__global__ __launch_bounds__(256, 2)
void bhl_main_kernel(const float* __restrict__ X) {
    extern __shared__ char dynsmem[];

    const int tid  = threadIdx.x;
    const int bid  = blockIdx.x;

    if (bid >= GRID_MAIN) {
        corr_block(dynsmem, X, bid - GRID_MAIN, tid);
        return;
    }

    const int lane = tid & 31;
    const int wid  = tid >> 5;
    const int wm   = wid >> 2;
    const int wn   = wid & 3;

    const int pstart = bid * 7 + min(bid, 8);
    const int pcount = 7 + (bid < 8 ? 1 : 0);

    int I = 0, s = 0;
    while (s + (NBLK - I) <= pstart) { s += NBLK - I; I++; }
    int J = I + (pstart - s);

    const uint32_t sb = (uint32_t)__cvta_generic_to_shared(dynsmem);
    const uint32_t aBase = sb;
    const uint32_t bBase = sb + ATILE;

    const char* Xb = (const char*)g_Xb;

    load_tileA(aBase, Xb + (size_t)I * BM * 512, tid);
    load_chunkB(bBase, Xb + (size_t)J * BM * 512, 0, tid);
    CP_COMMIT();
    load_chunkB(bBase + KCHUNK, Xb + (size_t)J * BM * 512, 1, tid);
    CP_COMMIT();

    uint32_t acc[4][4][2];                     // f16x2 accumulators
#pragma unroll
    for (int a = 0; a < 4; a++)
#pragma unroll
        for (int b = 0; b < 4; b++) { acc[a][b][0] = 0; acc[a][b][1] = 0; }

    unsigned long long G2, C4_2, C3_2, C2_2, ONE2, ZERO2;
    unsigned long long accR[8], colAcc[4];
    {
        const float g = GAMMA, c4 = 1.0f / 24.0f, c3 = 1.0f / 6.0f, c2 = 0.5f, o = 1.0f, z = 0.0f;
        PACK2(G2, g, g); PACK2(C4_2, c4, c4); PACK2(C3_2, c3, c3);
        PACK2(C2_2, c2, c2); PACK2(ONE2, o, o); PACK2(ZERO2, z, z);
#pragma unroll
        for (int i = 0; i < 8; i++) accR[i] = ZERO2;
#pragma unroll
        for (int i = 0; i < 4; i++) colAcc[i] = ZERO2;
    }

    int oldI = 0, oldJ = 0;
    bool haveOld = false;
    bool reloadedA = false;
    int gchunk = 0;

    auto epilogue_and_colflush = [&]() {
#pragma unroll
        for (int mt = 0; mt < 4; mt++) {
#pragma unroll
            for (int nt = 0; nt < 4; nt++) {
                unsigned long long d2, w2, e2;
                float2 f0 = __half22float2(u32_as_h2(acc[mt][nt][0]));   // rows-lo
                PACK2(d2, f0.x, f0.y);
                MUL2(w2, d2, G2);
                FMA2(e2, w2, C4_2, C3_2);
                FMA2(e2, e2, w2, C2_2);
                FMA2(e2, e2, w2, ONE2);
                FMA2(e2, e2, w2, ONE2);
                ADD2(accR[mt * 2], accR[mt * 2], e2);
                ADD2(colAcc[nt], colAcc[nt], e2);

                float2 f1 = __half22float2(u32_as_h2(acc[mt][nt][1]));   // rows-hi
                PACK2(d2, f1.x, f1.y);
                MUL2(w2, d2, G2);
                FMA2(e2, w2, C4_2, C3_2);
                FMA2(e2, e2, w2, C2_2);
                FMA2(e2, e2, w2, ONE2);
                FMA2(e2, e2, w2, ONE2);
                ADD2(accR[mt * 2 + 1], accR[mt * 2 + 1], e2);
                ADD2(colAcc[nt], colAcc[nt], e2);
            }
        }
        if (oldI != oldJ) {
#pragma unroll
            for (int nt = 0; nt < 4; nt++) {
                float vlo, vhi;
                UNPACK2(vlo, vhi, colAcc[nt]);
#pragma unroll
                for (int o = 4; o <= 16; o <<= 1) {
                    vlo += __shfl_xor_sync(0xffffffffu, vlo, o);
                    vhi += __shfl_xor_sync(0xffffffffu, vhi, o);
                }
                if (lane < 4) {
                    atomicAdd(&g_all[oldJ * BM + wn * 32 + nt * 8 + 2 * lane], vlo);
                    atomicAdd(&g_all[oldJ * BM + wn * 32 + nt * 8 + 2 * lane + 1], vhi);
                }
                colAcc[nt] = ZERO2;
            }
        } else {
#pragma unroll
            for (int nt = 0; nt < 4; nt++) colAcc[nt] = ZERO2;
        }
    };

    auto rowflush = [&](int Iblk) {
#pragma unroll
        for (int i = 0; i < 8; i++) {
            float vlo, vhi;
            UNPACK2(vlo, vhi, accR[i]);
            float v = vlo + vhi;
            v += __shfl_xor_sync(0xffffffffu, v, 1);
            v += __shfl_xor_sync(0xffffffffu, v, 2);
            if ((lane & 3) == 0) {
                int r = wm * 64 + (i >> 1) * 16 + (lane >> 2) + (i & 1) * 8;
                atomicAdd(&g_all[Iblk * BM + r], v);
            }
            accR[i] = ZERO2;
        }
    };

    for (int pi = 0; pi < pcount; ++pi) {
        const bool last = (pi == pcount - 1);
        int In = I, Jn = J + 1;
        if (Jn == NBLK) { In = I + 1; Jn = In; }
        const char* Brow  = Xb + (size_t)J  * BM * 512;
        const char* BrowN = Xb + (size_t)Jn * BM * 512;

#pragma unroll
        for (int kc = 0; kc < 4; kc++) {
            if (kc == 0 && reloadedA) { CP_WAIT(0); reloadedA = false; }
            else { CP_WAIT(1); }
            __syncthreads();

            if (kc == 0 && haveOld) { epilogue_and_colflush(); haveOld = false; }

            const uint32_t aC = aBase + (uint32_t)kc * KCHUNK;
            const uint32_t bC = bBase + (uint32_t)(gchunk & 1) * KCHUNK;

#pragma unroll
            for (int ks = 0; ks < 4; ks++) {
                uint32_t af[4][4];
#pragma unroll
                for (int mt = 0; mt < 4; mt++) {
                    int row = wm * 64 + mt * 16 + (lane & 15);
                    int kseg = ks * 2 + (lane >> 4);
                    uint32_t addr = aC + SW128(row * 128 + kseg * 16);
                    asm volatile("ldmatrix.sync.aligned.m8n8.x4.shared.b16 {%0,%1,%2,%3}, [%4];\n"
                                 : "=r"(af[mt][0]), "=r"(af[mt][1]), "=r"(af[mt][2]), "=r"(af[mt][3])
                                 : "r"(addr));
                }
#pragma unroll
                for (int np = 0; np < 2; np++) {
                    int g = lane >> 3, r = lane & 7;
                    int n = wn * 32 + np * 16 + (g >> 1) * 8 + r;
                    int kseg = ks * 2 + (g & 1);
                    uint32_t b0, b1, b2, b3;
                    uint32_t addr = bC + SW128(n * 128 + kseg * 16);
                    asm volatile("ldmatrix.sync.aligned.m8n8.x4.shared.b16 {%0,%1,%2,%3}, [%4];\n"
                                 : "=r"(b0), "=r"(b1), "=r"(b2), "=r"(b3) : "r"(addr));
                    if (kc == 0 && ks == 0) {
#pragma unroll
                        for (int mt = 0; mt < 4; mt++) {
                            asm volatile(
                                "mma.sync.aligned.m16n8k16.row.col.f16.f16.f16.f16 "
                                "{%0,%1}, {%2,%3,%4,%5}, {%6,%7}, {%8,%8};\n"
                                : "=r"(acc[mt][2 * np][0]), "=r"(acc[mt][2 * np][1])
                                : "r"(af[mt][0]), "r"(af[mt][1]), "r"(af[mt][2]), "r"(af[mt][3]),
                                  "r"(b0), "r"(b1), "r"(0u));
                            asm volatile(
                                "mma.sync.aligned.m16n8k16.row.col.f16.f16.f16.f16 "
                                "{%0,%1}, {%2,%3,%4,%5}, {%6,%7}, {%8,%8};\n"
                                : "=r"(acc[mt][2 * np + 1][0]), "=r"(acc[mt][2 * np + 1][1])
                                : "r"(af[mt][0]), "r"(af[mt][1]), "r"(af[mt][2]), "r"(af[mt][3]),
                                  "r"(b2), "r"(b3), "r"(0u));
                        }
                    } else {
#pragma unroll
                        for (int mt = 0; mt < 4; mt++) {
                            asm volatile(
                                "mma.sync.aligned.m16n8k16.row.col.f16.f16.f16.f16 "
                                "{%0,%1}, {%2,%3,%4,%5}, {%6,%7}, {%0,%1};\n"
                                : "+r"(acc[mt][2 * np][0]), "+r"(acc[mt][2 * np][1])
                                : "r"(af[mt][0]), "r"(af[mt][1]), "r"(af[mt][2]), "r"(af[mt][3]),
                                  "r"(b0), "r"(b1));
                            asm volatile(
                                "mma.sync.aligned.m16n8k16.row.col.f16.f16.f16.f16 "
                                "{%0,%1}, {%2,%3,%4,%5}, {%6,%7}, {%0,%1};\n"
                                : "+r"(acc[mt][2 * np + 1][0]), "+r"(acc[mt][2 * np + 1][1])
                                : "r"(af[mt][0]), "r"(af[mt][1]), "r"(af[mt][2]), "r"(af[mt][3]),
                                  "r"(b2), "r"(b3));
                        }
                    }
                }
            }
            __syncthreads();                   // all reads of this B buffer done

            uint32_t pSlot = bBase + (uint32_t)(gchunk & 1) * KCHUNK;
            if (kc < 2) {
                load_chunkB(pSlot, Brow, kc + 2, tid);
            } else if (!last) {
                load_chunkB(pSlot, BrowN, kc - 2, tid);
            }
            CP_COMMIT();
            gchunk++;
        }

        oldI = I; oldJ = J; haveOld = true;

        if (last) {
            epilogue_and_colflush(); haveOld = false;
            rowflush(I);
        } else if (In != I) {
            __syncthreads();
            epilogue_and_colflush(); haveOld = false;
            rowflush(I);
            load_tileA(aBase, Xb + (size_t)In * BM * 512, tid);
            CP_COMMIT();
            reloadedA = true;
        }
        I = In; J = Jn;
    }
}

__global__ void bhl_finalize_kernel(float* __restrict__ out) {
    __shared__ float red[256];
    const int tid = threadIdx.x;
    const int r = blockIdx.x * 256 + tid;
    red[tid] = __logf(g_pos[r] * (g_all[r] - g_same[r]));
    __syncthreads();
    for (int o = 128; o; o >>= 1) {
        if (tid < o) red[tid] += red[tid + o];
        __syncthreads();
    }
    if (tid == 0) atomicAdd(out, red[0] * (1.0f / (float)BATCH));
}

extern "C" void kernel_launch(void* const* d_in, const int* in_sizes, int n_in,
                              void* d_out, int out_size) {
    const float* X = (const float*)d_in[0];
    const int*   T = (const int*)d_in[1];
    float* out = (float*)d_out;

    cudaFuncSetAttribute(bhl_main_kernel, cudaFuncAttributeMaxDynamicSharedMemorySize, SMEM_DYN);

    bhl_convert_kernel<<<(BATCH * DIMK / 4) / 256, 256>>>(X, T, out);
    bhl_main_kernel<<<GRID_ALL, 256, SMEM_DYN>>>(X);
    bhl_finalize_kernel<<<BATCH / 256, 256>>>(out);
}